// round 12
// baseline (speedup 1.0000x reference)
#include <cuda_runtime.h>
#include <cuda_bf16.h>
#include <math_constants.h>

#define NNODES 100000
#define FIN 512
#define F1 16
#define F2P 8   // 7 padded to 8

// ---------------- scratch (no allocations allowed) ----------------
__device__ __align__(16) float g_deg[NNODES];        // raw degree (self-loop incl.)
__device__ __align__(16) float g_y1[NNODES * F1];    // dinv[r] * xw1[r]  (gather src)
__device__ __align__(16) float g_acc1[NNODES * F1];  // y1[c] + sum y1[r] (scatter dst)
__device__ __align__(16) float g_y2[NNODES * F2P];
__device__ __align__(16) float g_acc2[NNODES * F2P];
__device__ int g_is64;   // edge_index dtype flag (1 = int64, 0 = int32)

// ---------------- helpers ----------------
__device__ __forceinline__ void red_v4(float* p, float a, float b, float c, float d) {
    asm volatile("red.global.add.v4.f32 [%0], {%1, %2, %3, %4};"
                 :: "l"(p), "f"(a), "f"(b), "f"(c), "f"(d) : "memory");
}
__device__ __forceinline__ unsigned long long fma2(unsigned long long a,
                                                   unsigned long long b,
                                                   unsigned long long c) {
    unsigned long long d;
    asm("fma.rn.f32x2 %0, %1, %2, %3;" : "=l"(d) : "l"(a), "l"(b), "l"(c));
    return d;
}
__device__ __forceinline__ unsigned long long mul2(unsigned long long a,
                                                   unsigned long long b) {
    unsigned long long d;
    asm("mul.rn.f32x2 %0, %1, %2;" : "=l"(d) : "l"(a), "l"(b));
    return d;
}
__device__ __forceinline__ unsigned long long pack2(float x) {
    unsigned long long d;
    unsigned xi = __float_as_uint(x);
    asm("mov.b64 %0, {%1, %1};" : "=l"(d) : "r"(xi));
    return d;
}

// Layout: planar [all sources | all targets], E entries per block.
__device__ __forceinline__ void load_edge(const void* ei, int E, int e,
                                          int& r, int& c) {
    if (g_is64) {
        const long long* p = (const long long*)ei;
        r = (int)p[e];
        c = (int)p[(size_t)E + e];
    } else {
        const int* p = (const int*)ei;
        r = p[e];
        c = p[(size_t)E + e];
    }
}
__device__ __forceinline__ int load_col(const void* ei, int E, int e) {
    if (g_is64) return (int)((const long long*)ei)[(size_t)E + e];
    return ((const int*)ei)[(size_t)E + e];
}

// ---------------- kernels ----------------

// fused: dtype probe (thread 0 of block 0) + degree init (all threads).
// int32 data viewed as int64 has a random-id hi word -> probe fails at i=0.
__global__ void k_setup(const void* ei, int n) {
    int i = blockIdx.x * blockDim.x + threadIdx.x;
    if (i == 0) {
        const long long* p = (const long long*)ei;
        int ok = 1;
        for (int j = 0; j < 1024; j++) {
            long long v = p[j];
            if (v < 0 || v >= (long long)n) { ok = 0; break; }
        }
        g_is64 = ok;
    }
    if (i < n) g_deg[i] = 1.0f;   // self-loop contributes 1
}

__global__ void k_deg(const void* __restrict__ ei, int E, int n) {
    int e = blockIdx.x * blockDim.x + threadIdx.x;
    if (e >= E) return;
    int c = load_col(ei, E, e);
    if ((unsigned)c >= (unsigned)n) return;
    atomicAdd(&g_deg[c], 1.0f);
}

// y1 = rsqrt(deg[row]) * (x @ W1), dual-stored to g_y1 and g_acc1.
// Packed f32x2 math; W1 staged in smem as f32-pair u64s.
__global__ void __launch_bounds__(256) k_gemm1(const float* __restrict__ x,
                                               const float* __restrict__ W,
                                               int n) {
    __shared__ __align__(16) unsigned long long sW[FIN * 8];  // 32 KB
    {
        const ulonglong2* Wv = (const ulonglong2*)W;
        ulonglong2* sWv = (ulonglong2*)sW;
        for (int i = threadIdx.x; i < FIN * 4; i += 256) sWv[i] = Wv[i];
    }
    __syncthreads();

    int row = blockIdx.x * 256 + threadIdx.x;
    if (row >= n) return;

    unsigned long long acc[8];
#pragma unroll
    for (int f = 0; f < 8; f++) acc[f] = 0ull;

    const float4* xr = (const float4*)(x + (size_t)row * FIN);
#pragma unroll 2
    for (int k4 = 0; k4 < FIN / 4; k4++) {
        float4 xv = xr[k4];
#pragma unroll
        for (int d = 0; d < 4; d++) {
            float xk = (d == 0) ? xv.x : (d == 1) ? xv.y : (d == 2) ? xv.z : xv.w;
            unsigned long long xx = pack2(xk);
            const ulonglong2* wp = (const ulonglong2*)&sW[(k4 * 4 + d) * 8];
            ulonglong2 wa = wp[0], wb = wp[1];
            acc[0] = fma2(xx, wa.x, acc[0]);
            acc[1] = fma2(xx, wa.y, acc[1]);
            acc[2] = fma2(xx, wb.x, acc[2]);
            acc[3] = fma2(xx, wb.y, acc[3]);
            ulonglong2 wc = wp[2], wd = wp[3];
            acc[4] = fma2(xx, wc.x, acc[4]);
            acc[5] = fma2(xx, wc.y, acc[5]);
            acc[6] = fma2(xx, wd.x, acc[6]);
            acc[7] = fma2(xx, wd.y, acc[7]);
        }
    }

    unsigned long long dd = pack2(rsqrtf(g_deg[row]));
    ulonglong2* o1 = (ulonglong2*)(g_y1 + (size_t)row * F1);
    ulonglong2* o2 = (ulonglong2*)(g_acc1 + (size_t)row * F1);
#pragma unroll
    for (int q = 0; q < 4; q++) {
        ulonglong2 v;
        v.x = mul2(acc[q * 2 + 0], dd);
        v.y = mul2(acc[q * 2 + 1], dd);
        o1[q] = v;
        o2[q] = v;
    }
}

// layer-1 edge scatter, 4 THREADS PER EDGE (one float4 chunk each).
// Consecutive lanes cover consecutive 16B chunks of the SAME source row ->
// a warp's LDG.128 touches ~8 distinct 128B lines instead of 32 (fewer
// L1tex wavefront replays); same shape on the RED side.
__global__ void k_scatter1(const void* __restrict__ ei, int E, int n) {
    int t = blockIdx.x * blockDim.x + threadIdx.x;
    int e = t >> 2;
    int j = t & 3;
    if (e >= E) return;
    int r, c;
    load_edge(ei, E, e, r, c);   // adjacent lanes same addr -> L1 broadcast
    if ((unsigned)r >= (unsigned)n || (unsigned)c >= (unsigned)n) return;
    float4 v = *(const float4*)(g_y1 + (size_t)r * F1 + j * 4);
    red_v4(g_acc1 + (size_t)c * F1 + j * 4, v.x, v.y, v.z, v.w);
}

// h = relu(b1 + dinv*acc1); y2 = dinv*(h @ W2); dual store.
__global__ void k_layer2(const float* __restrict__ W2,
                         const float* __restrict__ b1, int n) {
    int i = blockIdx.x * blockDim.x + threadIdx.x;
    if (i >= n) return;
    float di = rsqrtf(g_deg[i]);
    float h[16];
    const float4* p = (const float4*)(g_acc1 + (size_t)i * F1);
#pragma unroll
    for (int q = 0; q < 4; q++) {
        float4 v = p[q];
        h[q * 4 + 0] = fmaxf(__ldg(&b1[q * 4 + 0]) + di * v.x, 0.f);
        h[q * 4 + 1] = fmaxf(__ldg(&b1[q * 4 + 1]) + di * v.y, 0.f);
        h[q * 4 + 2] = fmaxf(__ldg(&b1[q * 4 + 2]) + di * v.z, 0.f);
        h[q * 4 + 3] = fmaxf(__ldg(&b1[q * 4 + 3]) + di * v.w, 0.f);
    }
    float s[7] = {0.f, 0.f, 0.f, 0.f, 0.f, 0.f, 0.f};
#pragma unroll
    for (int k = 0; k < 16; k++) {
        float hk = h[k];
#pragma unroll
        for (int f = 0; f < 7; f++) s[f] += hk * __ldg(&W2[k * 7 + f]);
    }
    float4 v0 = make_float4(di * s[0], di * s[1], di * s[2], di * s[3]);
    float4 v1 = make_float4(di * s[4], di * s[5], di * s[6], 0.f);
    float4* oy = (float4*)(g_y2 + (size_t)i * F2P);
    float4* oa = (float4*)(g_acc2 + (size_t)i * F2P);
    oy[0] = v0; oy[1] = v1;
    oa[0] = v0; oa[1] = v1;
}

// layer-2 edge scatter, 2 THREADS PER EDGE.
__global__ void k_scatter2(const void* __restrict__ ei, int E, int n) {
    int t = blockIdx.x * blockDim.x + threadIdx.x;
    int e = t >> 1;
    int j = t & 1;
    if (e >= E) return;
    int r, c;
    load_edge(ei, E, e, r, c);
    if ((unsigned)r >= (unsigned)n || (unsigned)c >= (unsigned)n) return;
    float4 v = *(const float4*)(g_y2 + (size_t)r * F2P + j * 4);
    red_v4(g_acc2 + (size_t)c * F2P + j * 4, v.x, v.y, v.z, v.w);
}

// w = b2 + dinv*acc2; log_softmax
__global__ void k_logsoftmax(const float* __restrict__ b2,
                             float* __restrict__ out, int n) {
    int i = blockIdx.x * blockDim.x + threadIdx.x;
    if (i >= n) return;
    float di = rsqrtf(g_deg[i]);
    const float4* p = (const float4*)(g_acc2 + (size_t)i * F2P);
    float4 a0 = p[0], a1 = p[1];
    float w[7];
    w[0] = __ldg(&b2[0]) + di * a0.x;
    w[1] = __ldg(&b2[1]) + di * a0.y;
    w[2] = __ldg(&b2[2]) + di * a0.z;
    w[3] = __ldg(&b2[3]) + di * a0.w;
    w[4] = __ldg(&b2[4]) + di * a1.x;
    w[5] = __ldg(&b2[5]) + di * a1.y;
    w[6] = __ldg(&b2[6]) + di * a1.z;
    float m = w[0];
#pragma unroll
    for (int f = 1; f < 7; f++) m = fmaxf(m, w[f]);
    float s = 0.f;
#pragma unroll
    for (int f = 0; f < 7; f++) s += expf(w[f] - m);
    float l = logf(s);
    float* o = out + (size_t)i * 7;
#pragma unroll
    for (int f = 0; f < 7; f++) o[f] = w[f] - m - l;
}

// ---------------- launch ----------------
// Inputs identified BY ELEMENT COUNT (x largest, edge_index second largest,
// W1=8192, W2=112, b1=16, b2=7); positional fallback otherwise.
extern "C" void kernel_launch(void* const* d_in, const int* in_sizes, int n_in,
                              void* d_out, int out_size) {
    const void* x  = d_in[0];
    const void* ei = d_in[1];
    const void* W1 = d_in[2];
    const void* b1 = d_in[3];
    const void* W2 = d_in[4];
    const void* b2 = d_in[5];
    int x_sz = in_sizes[0], e_sz = in_sizes[1];

    if (n_in >= 6) {
        int ix = 0;
        for (int i = 1; i < n_in; i++) if (in_sizes[i] > in_sizes[ix]) ix = i;
        int ie = (ix == 0) ? 1 : 0;
        for (int i = 0; i < n_in; i++)
            if (i != ix && in_sizes[i] > in_sizes[ie]) ie = i;
        x = d_in[ix]; x_sz = in_sizes[ix];
        ei = d_in[ie]; e_sz = in_sizes[ie];
        for (int i = 0; i < n_in; i++) {
            if (i == ix || i == ie) continue;
            switch (in_sizes[i]) {
                case 8192: W1 = d_in[i]; break;   // 512*16
                case 112:  W2 = d_in[i]; break;   // 16*7
                case 16:   b1 = d_in[i]; break;
                case 7:    b2 = d_in[i]; break;
                default: break;
            }
        }
    }

    int n = x_sz / FIN;   // 100000
    int E = e_sz / 2;     // 3200000 edges (planar [src | dst])

    const int T = 256;
    int gbN  = (n + T - 1) / T;
    int gbE  = (E + T - 1) / T;
    int gbE4 = ((E * 4) + T - 1) / T;   // 4 threads/edge
    int gbE2 = ((E * 2) + T - 1) / T;   // 2 threads/edge

    k_setup<<<gbN, T>>>(ei, n);
    k_deg<<<gbE, T>>>(ei, E, n);
    k_gemm1<<<gbN, T>>>((const float*)x, (const float*)W1, n);
    k_scatter1<<<gbE4, T>>>(ei, E, n);
    k_layer2<<<gbN, T>>>((const float*)W2, (const float*)b1, n);
    k_scatter2<<<gbE2, T>>>(ei, E, n);
    k_logsoftmax<<<gbN, T>>>((const float*)b2, (float*)d_out, n);
}